// round 3
// baseline (speedup 1.0000x reference)
#include <cuda_runtime.h>

// Problem constants (fixed by the dataset generator).
#define NN   40000
#define EE   640000
#define FIN  128
#define FHID 512
#define FOUT 256

// ---------------- scratch (static device globals; no allocation allowed) ----
__device__ int   g_is64;
__device__ int   g_src[EE];
__device__ int   g_dst[EE];
__device__ int   g_cnt[NN];
__device__ int   g_rowptr[NN + 1];
__device__ int   g_cursor[NN];
__device__ int   g_col[EE];
__device__ float g_aggA[(size_t)NN * FIN];   // mean-aggregated x        (20 MB)
__device__ float g_h   [(size_t)NN * FHID];  // layer-1 output           (82 MB)
__device__ float g_p   [(size_t)NN * FOUT];  // h @ W2l                  (40 MB)
__device__ float g_agg2[(size_t)NN * FOUT];  // mean-aggregated p        (40 MB)

// ---------------- edge dtype detection + conversion ---------------------------
// If edge_index is int64 (little-endian, values < 40000), every odd int32 word
// of the first 64 entries is 0. If it is int32, those words are random node ids.
__global__ void detect_kernel(const int* __restrict__ ei32) {
    if (threadIdx.x == 0 && blockIdx.x == 0) {
        int all0 = 1;
        for (int i = 0; i < 64; i++)
            if (ei32[2 * i + 1] != 0) all0 = 0;
        g_is64 = all0;
    }
}

__global__ void convert_kernel(const int* __restrict__ ei32) {
    int e = blockIdx.x * blockDim.x + threadIdx.x;
    if (e >= EE) return;
    int is64 = g_is64;
    int s, d;
    if (is64) {
        const long long* ei64 = (const long long*)ei32;
        s = (int)ei64[e];
        d = (int)ei64[EE + e];
    } else {
        s = ei32[e];
        d = ei32[EE + e];
    }
    g_src[e] = s;
    g_dst[e] = d;
}

// ---------------- CSR build --------------------------------------------------
__global__ void zero_cnt_kernel() {
    int i = blockIdx.x * blockDim.x + threadIdx.x;
    if (i < NN) g_cnt[i] = 0;
}

__global__ void hist_kernel() {
    int e = blockIdx.x * blockDim.x + threadIdx.x;
    if (e < EE) atomicAdd(&g_cnt[g_dst[e]], 1);
}

// One-block exclusive scan: each thread owns a contiguous chunk, serial-sums it,
// block-scans the 1024 partials, then writes running prefixes back.
__global__ void scan_kernel() {
    const int T = 1024;
    const int CH = (NN + T - 1) / T;  // 40
    __shared__ int s[T];
    int t = threadIdx.x;
    int base = t * CH;

    int sum = 0;
    for (int j = 0; j < CH; j++) {
        int i = base + j;
        if (i < NN) sum += g_cnt[i];
    }
    s[t] = sum;
    __syncthreads();
    for (int off = 1; off < T; off <<= 1) {
        int v = (t >= off) ? s[t - off] : 0;
        __syncthreads();
        s[t] += v;
        __syncthreads();
    }
    int run = s[t] - sum;  // exclusive prefix for this thread's chunk
    for (int j = 0; j < CH; j++) {
        int i = base + j;
        if (i < NN) {
            g_rowptr[i] = run;
            g_cursor[i] = run;
            run += g_cnt[i];
        }
    }
    if (t == 0) g_rowptr[NN] = EE;
}

__global__ void fill_kernel() {
    int e = blockIdx.x * blockDim.x + threadIdx.x;
    if (e < EE) {
        int d   = g_dst[e];
        int pos = atomicAdd(&g_cursor[d], 1);
        g_col[pos] = g_src[e];
    }
}

// ---------------- mean aggregation over CSR ----------------------------------
// One warp per node. Lane l owns float4 chunk(s) of the feature row.
// VPL = float4 chunks per lane (1 -> F=128, 2 -> F=256).
template <int VPL>
__global__ void agg_kernel(const float* __restrict__ feat,
                           float* __restrict__ out) {
    int node = blockIdx.x * (blockDim.x >> 5) + (threadIdx.x >> 5);
    if (node >= NN) return;
    int lane = threadIdx.x & 31;
    int beg = g_rowptr[node];
    int end = g_rowptr[node + 1];

    const int F = VPL * 128;
    float4 acc[VPL];
#pragma unroll
    for (int v = 0; v < VPL; v++) acc[v] = make_float4(0.f, 0.f, 0.f, 0.f);

    for (int j = beg; j < end; j++) {
        int sidx = __ldg(&g_col[j]);
        const float4* row = (const float4*)(feat + (size_t)sidx * F);
#pragma unroll
        for (int v = 0; v < VPL; v++) {
            float4 r = row[lane + v * 32];
            acc[v].x += r.x; acc[v].y += r.y; acc[v].z += r.z; acc[v].w += r.w;
        }
    }
    float inv = 1.0f / (float)max(end - beg, 1);
    float4* o = (float4*)(out + (size_t)node * F);
#pragma unroll
    for (int v = 0; v < VPL; v++) {
        acc[v].x *= inv; acc[v].y *= inv; acc[v].z *= inv; acc[v].w *= inv;
        o[lane + v * 32] = acc[v];
    }
}

// ---------------- fp32 SIMT GEMM ----------------------------------------------
// C[M,N] = A1[M,K] @ B1[K,N]  (+ A2[M,K] @ B2[K,N])  (+ bias[N]) (+ D[M,N]) (relu?)
// Row-major everywhere. BM=128, BN=64, BK=16, 256 threads, 8x4 micro-tile.
__global__ void __launch_bounds__(256)
gemm_kernel(const float* __restrict__ A1, const float* __restrict__ B1,
            const float* __restrict__ A2, const float* __restrict__ B2,
            const float* __restrict__ bias, const float* __restrict__ D,
            float* __restrict__ C, int M, int N, int K, int relu) {
    const int BM = 128, BN = 64, BK = 16;
    __shared__ __align__(16) float As[BK][BM];  // transposed A tile
    __shared__ __align__(16) float Bs[BK][BN];

    int tid = threadIdx.x;
    int m0 = blockIdx.y * BM;
    int n0 = blockIdx.x * BN;
    int ty = tid >> 4;   // 0..15 -> m offset ty*8
    int tx = tid & 15;   // 0..15 -> n offset tx*4

    float acc[8][4];
#pragma unroll
    for (int i = 0; i < 8; i++)
#pragma unroll
        for (int j = 0; j < 4; j++) acc[i][j] = 0.f;

    for (int ph = 0; ph < 2; ph++) {
        const float* A = ph ? A2 : A1;
        const float* B = ph ? B2 : B1;
        if (A == nullptr) break;

        int ktiles = K / BK;
        // register-prefetch software pipeline
        float4 pa[2];
        float4 pb;
        {
#pragma unroll
            for (int u = 0; u < 2; u++) {
                int f = tid + u * 256;          // float4 id in [0,512)
                int r = f >> 2, kc = f & 3;
                int gm = m0 + r;
                pa[u] = (gm < M) ? *(const float4*)(A + (size_t)gm * K + kc * 4)
                                 : make_float4(0.f, 0.f, 0.f, 0.f);
            }
            int r = tid >> 4, nc = tid & 15;
            pb = *(const float4*)(B + (size_t)r * N + n0 + nc * 4);
        }

        for (int kt = 0; kt < ktiles; kt++) {
            // commit prefetched tile to smem
#pragma unroll
            for (int u = 0; u < 2; u++) {
                int f = tid + u * 256;
                int r = f >> 2, kc = f & 3;
                As[kc * 4 + 0][r] = pa[u].x;
                As[kc * 4 + 1][r] = pa[u].y;
                As[kc * 4 + 2][r] = pa[u].z;
                As[kc * 4 + 3][r] = pa[u].w;
            }
            {
                int r = tid >> 4, nc = tid & 15;
                *(float4*)&Bs[r][nc * 4] = pb;
            }
            __syncthreads();

            // prefetch next tile
            if (kt + 1 < ktiles) {
                int k0n = (kt + 1) * BK;
#pragma unroll
                for (int u = 0; u < 2; u++) {
                    int f = tid + u * 256;
                    int r = f >> 2, kc = f & 3;
                    int gm = m0 + r;
                    pa[u] = (gm < M)
                                ? *(const float4*)(A + (size_t)gm * K + k0n + kc * 4)
                                : make_float4(0.f, 0.f, 0.f, 0.f);
                }
                int r = tid >> 4, nc = tid & 15;
                pb = *(const float4*)(B + (size_t)(k0n + r) * N + n0 + nc * 4);
            }

#pragma unroll
            for (int kk = 0; kk < BK; kk++) {
                float a[8], b[4];
                *(float4*)&a[0] = *(const float4*)&As[kk][ty * 8];
                *(float4*)&a[4] = *(const float4*)&As[kk][ty * 8 + 4];
                *(float4*)&b[0] = *(const float4*)&Bs[kk][tx * 4];
#pragma unroll
                for (int i = 0; i < 8; i++)
#pragma unroll
                    for (int j = 0; j < 4; j++) acc[i][j] += a[i] * b[j];
            }
            __syncthreads();
        }
    }

    // epilogue
#pragma unroll
    for (int i = 0; i < 8; i++) {
        int m = m0 + ty * 8 + i;
        if (m < M) {
            int n = n0 + tx * 4;
            float4 o;
            o.x = acc[i][0]; o.y = acc[i][1]; o.z = acc[i][2]; o.w = acc[i][3];
            if (bias) {
                const float4 bv = *(const float4*)(bias + n);
                o.x += bv.x; o.y += bv.y; o.z += bv.z; o.w += bv.w;
            }
            if (D) {
                const float4 dv = *(const float4*)(D + (size_t)m * N + n);
                o.x += dv.x; o.y += dv.y; o.z += dv.z; o.w += dv.w;
            }
            if (relu) {
                o.x = fmaxf(o.x, 0.f); o.y = fmaxf(o.y, 0.f);
                o.z = fmaxf(o.z, 0.f); o.w = fmaxf(o.w, 0.f);
            }
            *(float4*)(C + (size_t)m * N + n) = o;
        }
    }
}

// ---------------- launcher -----------------------------------------------------
extern "C" void kernel_launch(void* const* d_in, const int* in_sizes, int n_in,
                              void* d_out, int out_size) {
    const float* x   = (const float*)d_in[0];
    const int*   ei  = (const int*)d_in[1];   // int32 OR int64 (detected on device)
    const float* W1l = (const float*)d_in[2];
    const float* b1  = (const float*)d_in[3];
    const float* W1r = (const float*)d_in[4];
    const float* W2l = (const float*)d_in[5];
    const float* b2  = (const float*)d_in[6];
    const float* W2r = (const float*)d_in[7];
    float* out = (float*)d_out;

    float *aggA, *h, *p, *agg2;
    cudaGetSymbolAddress((void**)&aggA, g_aggA);
    cudaGetSymbolAddress((void**)&h,    g_h);
    cudaGetSymbolAddress((void**)&p,    g_p);
    cudaGetSymbolAddress((void**)&agg2, g_agg2);

    // Edge dtype detection + normalization to int32
    detect_kernel<<<1, 32>>>(ei);
    convert_kernel<<<(EE + 255) / 256, 256>>>(ei);

    // CSR build (shared by both layers)
    zero_cnt_kernel<<<(NN + 255) / 256, 256>>>();
    hist_kernel<<<(EE + 255) / 256, 256>>>();
    scan_kernel<<<1, 1024>>>();
    fill_kernel<<<(EE + 255) / 256, 256>>>();

    // Layer 1: aggregate x (128 dims), then h = relu(aggA@W1l + x@W1r + b1)
    agg_kernel<1><<<(NN + 7) / 8, 256>>>(x, aggA);
    {
        dim3 grid(FHID / 64, (NN + 127) / 128);
        gemm_kernel<<<grid, 256>>>(aggA, W1l, x, W1r, b1, nullptr, h,
                                   NN, FHID, FIN, /*relu=*/1);
    }

    // Layer 2: p = h@W2l  (GEMM before aggregation: mean commutes with linear)
    {
        dim3 grid(FOUT / 64, (NN + 127) / 128);
        gemm_kernel<<<grid, 256>>>(h, W2l, nullptr, nullptr, nullptr, nullptr, p,
                                   NN, FOUT, FHID, /*relu=*/0);
    }
    // agg2 = scatter_mean(p)  (256 dims)
    agg_kernel<2><<<(NN + 7) / 8, 256>>>(p, agg2);
    // out = h@W2r + b2 + agg2
    {
        dim3 grid(FOUT / 64, (NN + 127) / 128);
        gemm_kernel<<<grid, 256>>>(h, W2r, nullptr, nullptr, b2, agg2, out,
                                   NN, FOUT, FHID, /*relu=*/0);
    }
}